// round 5
// baseline (speedup 1.0000x reference)
#include <cuda_runtime.h>
#include <float.h>

#define HW 4096
#define NB 4
#define FULLW 0xffffffffu

// ---------------- scratch (device globals: no allocations allowed) ----------
__device__ float g_qT[NB * HW * 8];        // [b][s][d]  512 KB
__device__ float g_kT[NB * HW * 8];        // [b][t][d]  512 KB
__device__ float g_xT[NB * HW * 64];       // [b][s][c]  4 MB
__device__ int   g_idx[NB * HW * 9];       // [b][t][9]  576 KB
__device__ float g_Wt[576 * 64];           // [kk*64+c][o] 147 KB

// ---------------- prep: weight transpose (OC,C,9) -> Wt[kk*64+c][o] ---------
__global__ void k_prep_w(const float* __restrict__ W) {
    int j = blockIdx.x * 256 + threadIdx.x;
    if (j >= 576 * 64) return;
    int r = j >> 6, o = j & 63;
    int kk = r >> 6, c = r & 63;
    g_Wt[j] = W[o * 576 + c * 9 + kk];
}

// ---------------- k1: 1x1 convs (q,k) + x transpose -------------------------
__global__ void k_proj(const float* __restrict__ x, const float* __restrict__ qw,
                       const float* __restrict__ qb, const float* __restrict__ kw,
                       const float* __restrict__ kb) {
    __shared__ float tile[64][129];
    __shared__ float wq[512], wk[512];
    int tid = threadIdx.x;
    int b  = blockIdx.x >> 5;
    int s0 = (blockIdx.x & 31) << 7;

    for (int u = tid; u < 512; u += 128) { wq[u] = qw[u]; wk[u] = kw[u]; }
    for (int u = tid; u < 64 * 128; u += 128) {
        int c = u >> 7, sl = u & 127;
        tile[c][sl] = x[(b * 64 + c) * HW + s0 + sl];
    }
    __syncthreads();

    for (int u = tid; u < 128 * 64; u += 128) {
        int sl = u >> 6, c = u & 63;
        g_xT[((size_t)b * HW + s0 + sl) * 64 + c] = tile[c][sl];
    }

    float qa[8], ka[8];
    #pragma unroll
    for (int d = 0; d < 8; ++d) { qa[d] = __ldg(qb + d); ka[d] = __ldg(kb + d); }
    int sl = tid;
    #pragma unroll 4
    for (int c = 0; c < 64; ++c) {
        float xv = tile[c][sl];
        #pragma unroll
        for (int d = 0; d < 8; ++d) {
            qa[d] = fmaf(wq[d * 64 + c], xv, qa[d]);
            ka[d] = fmaf(wk[d * 64 + c], xv, ka[d]);
        }
    }
    float4* qT4 = (float4*)g_qT;
    float4* kT4 = (float4*)g_kT;
    int base = (b * HW + s0 + sl) * 2;
    qT4[base]     = make_float4(qa[0], qa[1], qa[2], qa[3]);
    qT4[base + 1] = make_float4(qa[4], qa[5], qa[6], qa[7]);
    kT4[base]     = make_float4(ka[0], ka[1], ka[2], ka[3]);
    kT4[base + 1] = make_float4(ka[4], ka[5], ka[6], ka[7]);
}

// ---------------- top-9 insert: warp-uniform state -> real early-exit -------
// v[],ix[] are IDENTICAL across all lanes of the warp, so these branches are
// warp-uniform: no divergence, and we get true early exit instead of a
// 30-instruction fully-predicated compare-swap chain.
__device__ __forceinline__ void ins9e(float val, int s, float v[9], int ix[9]) {
    if (val > v[8]) {                    // strict: equal keeps earlier index
        #pragma unroll
        for (int j = 8; j > 0; --j) {
            if (v[j - 1] >= val) {       // found slot: place and stop
                v[j] = val; ix[j] = s;
                return;
            }
            v[j] = v[j - 1]; ix[j] = ix[j - 1];
        }
        v[0] = val; ix[0] = s;
    }
}

// ---------------- k2: energy GEMM -> smem, warp-uniform ballot top-9 --------
// grid 1024 (4 b x 256 tiles of 16 t), block 512 (16 warps).
__global__ void __launch_bounds__(512, 2) k_topk2() {
    extern __shared__ float sm2[];
    float4* qs4 = (float4*)sm2;            // 1024 float4 (16 KB)
    float*  ebuf = sm2 + 4096;             // 16 * 516 floats (33 KB)
    int tid  = threadIdx.x;
    int w    = tid >> 5, lane = tid & 31;
    int b    = blockIdx.x >> 8;
    int t0   = (blockIdx.x & 255) << 4;
    int tg   = lane & 15;                  // GEMM: lane -> t
    int sg   = lane >> 4;                  // GEMM: 2 s per step

    const float4* kT4 = (const float4*)g_kT;
    float4 kA = kT4[(b * HW + t0 + tg) * 2];
    float4 kB = kT4[(b * HW + t0 + tg) * 2 + 1];

    float v[9]; int ix[9];
    #pragma unroll
    for (int j = 0; j < 9; ++j) { v[j] = -FLT_MAX; ix[j] = -1; }

    const float4* qbase = ((const float4*)g_qT) + (size_t)b * HW * 2;
    for (int chunk = 0; chunk < 8; ++chunk) {
        int s0 = chunk << 9;
        qs4[tid]       = qbase[s0 * 2 + tid];
        qs4[tid + 512] = qbase[s0 * 2 + tid + 512];
        __syncthreads();                   // q ready AND prev-chunk scans done

        #pragma unroll 4
        for (int j = 0; j < 16; ++j) {
            int sl = (w << 5) + (j << 1) + sg;
            float4 A  = qs4[sl * 2];
            float4 Bq = qs4[sl * 2 + 1];
            float e  = kA.x * A.x;
            e  = fmaf(kA.y, A.y, e);
            e  = fmaf(kA.z, A.z, e);
            e  = fmaf(kA.w, A.w, e);
            float e2 = kB.x * Bq.x;
            e2 = fmaf(kB.y, Bq.y, e2);
            e2 = fmaf(kB.z, Bq.z, e2);
            e2 = fmaf(kB.w, Bq.w, e2);
            ebuf[tg * 516 + sl] = e + e2;
        }
        __syncthreads();                   // ebuf ready

        // scan: warp w owns row w (one t, warp-shared threshold)
        const float* row = ebuf + w * 516;
        #pragma unroll
        for (int g = 0; g < 4; ++g) {
            float4 ev = *(const float4*)(row + (g << 7) + (lane << 2));
            float m = fmaxf(fmaxf(ev.x, ev.y), fmaxf(ev.z, ev.w));
            unsigned bal = __ballot_sync(FULLW, m > v[8]);
            int sb0 = s0 + (g << 7);
            while (bal) {                  // warp-uniform loop
                int src = __ffs(bal) - 1; bal &= bal - 1;
                float c0 = __shfl_sync(FULLW, ev.x, src);
                float c1 = __shfl_sync(FULLW, ev.y, src);
                float c2 = __shfl_sync(FULLW, ev.z, src);
                float c3 = __shfl_sync(FULLW, ev.w, src);
                int sb = sb0 + (src << 2);
                ins9e(c0, sb,     v, ix);
                ins9e(c1, sb + 1, v, ix);
                ins9e(c2, sb + 2, v, ix);
                ins9e(c3, sb + 3, v, ix);
            }
        }
    }

    // sort indices ascending (reference sorts idx); uniform across warp
    #pragma unroll
    for (int p = 0; p < 8; ++p)
        #pragma unroll
        for (int j = 0; j < 8 - p; ++j)
            if (ix[j] > ix[j + 1]) {
                int ti = ix[j]; ix[j] = ix[j + 1]; ix[j + 1] = ti;
            }
    if (lane == 0) {
        #pragma unroll
        for (int j = 0; j < 9; ++j)
            g_idx[((size_t)b * HW + t0 + w) * 9 + j] = ix[j];
    }
}

// ---------------- k3: gather + 9-tap conv + relu + residual -----------------
// Register-tiled: 128 t x 64 o per block, thread = 4t x 4o. 9 chunks of 64 r
// with register-prefetched gather. Inner loop steps rl by 4 using LDS.128 for
// the g operands: 8 LDS.128 per 64 FFMA (was 20 loads).
__global__ void __launch_bounds__(512, 1) k_conv(const float* __restrict__ bias,
                                                 const float* __restrict__ gamma,
                                                 float* __restrict__ out) {
    extern __shared__ float sm[];
    float* Wsm  = sm;                          // 36864 floats
    float* gbuf = sm + 36864;                  // 128 rows x 68 floats
    int*   idxs = (int*)(sm + 36864 + 128 * 68);   // 1152 ints
    int tid = threadIdx.x;
    int b  = blockIdx.x >> 5;
    int t0 = (blockIdx.x & 31) << 7;

    for (int u = tid; u < 36864; u += 512) Wsm[u] = g_Wt[u];
    for (int u = tid; u < 1152; u += 512)
        idxs[u] = g_idx[((size_t)b * HW + t0) * 9 + u];

    int og = tid & 15;
    int tg = tid >> 4;
    float4 acc0 = make_float4(0.f,0.f,0.f,0.f);
    float4 acc1 = make_float4(0.f,0.f,0.f,0.f);
    float4 acc2 = make_float4(0.f,0.f,0.f,0.f);
    float4 acc3 = make_float4(0.f,0.f,0.f,0.f);

    const float4* xT4 = ((const float4*)g_xT) + (size_t)b * HW * 16;
    const float4* W4  = (const float4*)Wsm;
    float4* g4 = (float4*)gbuf;                // row stride 17 float4
    const float* gp0 = gbuf + (tg * 4 + 0) * 68;
    const float* gp1 = gbuf + (tg * 4 + 1) * 68;
    const float* gp2 = gbuf + (tg * 4 + 2) * 68;
    const float* gp3 = gbuf + (tg * 4 + 3) * 68;
    int c4  = tid & 15;
    int tl0 = tid >> 4;
    __syncthreads();                           // idxs ready

    float4 r0 = __ldcg(&xT4[idxs[(tl0     ) * 9] * 16 + c4]);
    float4 r1 = __ldcg(&xT4[idxs[(tl0 + 32) * 9] * 16 + c4]);
    float4 r2 = __ldcg(&xT4[idxs[(tl0 + 64) * 9] * 16 + c4]);
    float4 r3 = __ldcg(&xT4[idxs[(tl0 + 96) * 9] * 16 + c4]);

#define FMA16(GA, GB, GC, GD, WV)                                          \
    acc0.x = fmaf((WV).x, (GA), acc0.x); acc0.y = fmaf((WV).y, (GA), acc0.y); \
    acc0.z = fmaf((WV).z, (GA), acc0.z); acc0.w = fmaf((WV).w, (GA), acc0.w); \
    acc1.x = fmaf((WV).x, (GB), acc1.x); acc1.y = fmaf((WV).y, (GB), acc1.y); \
    acc1.z = fmaf((WV).z, (GB), acc1.z); acc1.w = fmaf((WV).w, (GB), acc1.w); \
    acc2.x = fmaf((WV).x, (GC), acc2.x); acc2.y = fmaf((WV).y, (GC), acc2.y); \
    acc2.z = fmaf((WV).z, (GC), acc2.z); acc2.w = fmaf((WV).w, (GC), acc2.w); \
    acc3.x = fmaf((WV).x, (GD), acc3.x); acc3.y = fmaf((WV).y, (GD), acc3.y); \
    acc3.z = fmaf((WV).z, (GD), acc3.z); acc3.w = fmaf((WV).w, (GD), acc3.w);

    for (int kk = 0; kk < 9; ++kk) {
        g4[(tl0     ) * 17 + c4] = r0;
        g4[(tl0 + 32) * 17 + c4] = r1;
        g4[(tl0 + 64) * 17 + c4] = r2;
        g4[(tl0 + 96) * 17 + c4] = r3;
        __syncthreads();                       // gbuf ready
        if (kk < 8) {                          // prefetch next, hidden by compute
            r0 = __ldcg(&xT4[idxs[(tl0     ) * 9 + kk + 1] * 16 + c4]);
            r1 = __ldcg(&xT4[idxs[(tl0 + 32) * 9 + kk + 1] * 16 + c4]);
            r2 = __ldcg(&xT4[idxs[(tl0 + 64) * 9 + kk + 1] * 16 + c4]);
            r3 = __ldcg(&xT4[idxs[(tl0 + 96) * 9 + kk + 1] * 16 + c4]);
        }
        int rg0 = kk << 6;
        #pragma unroll 2
        for (int rl = 0; rl < 64; rl += 4) {
            float4 ga = *(const float4*)(gp0 + rl);
            float4 gb = *(const float4*)(gp1 + rl);
            float4 gc = *(const float4*)(gp2 + rl);
            float4 gd = *(const float4*)(gp3 + rl);
            float4 w0 = W4[((rg0 + rl    ) << 4) + og];
            float4 w1 = W4[((rg0 + rl + 1) << 4) + og];
            float4 w2 = W4[((rg0 + rl + 2) << 4) + og];
            float4 w3 = W4[((rg0 + rl + 3) << 4) + og];
            FMA16(ga.x, gb.x, gc.x, gd.x, w0)
            FMA16(ga.y, gb.y, gc.y, gd.y, w1)
            FMA16(ga.z, gb.z, gc.z, gd.z, w2)
            FMA16(ga.w, gb.w, gc.w, gd.w, w3)
        }
        __syncthreads();                       // compute done before next store
    }
#undef FMA16

    float gamma0 = __ldg(gamma);
    float4 bv = __ldg(((const float4*)bias) + og);
    int o0 = og << 2;
    float4 accs[4] = {acc0, acc1, acc2, acc3};
    #pragma unroll
    for (int j = 0; j < 4; ++j) {
        int t = t0 + tg * 4 + j;
        float4 res = __ldcg(&((const float4*)g_xT)[((size_t)b * HW + t) * 16 + og]);
        float* outp = out + ((size_t)b * 64 + o0) * HW + t;
        outp[0]      = fmaf(gamma0, fmaxf(accs[j].x + bv.x, 0.f), res.x);
        outp[HW]     = fmaf(gamma0, fmaxf(accs[j].y + bv.y, 0.f), res.y);
        outp[2 * HW] = fmaf(gamma0, fmaxf(accs[j].z + bv.z, 0.f), res.z);
        outp[3 * HW] = fmaf(gamma0, fmaxf(accs[j].w + bv.w, 0.f), res.w);
    }
}

// ---------------- launch ----------------------------------------------------
extern "C" void kernel_launch(void* const* d_in, const int* in_sizes, int n_in,
                              void* d_out, int out_size) {
    const float* x      = (const float*)d_in[0];
    const float* qw     = (const float*)d_in[1];
    const float* qb     = (const float*)d_in[2];
    const float* kw     = (const float*)d_in[3];
    const float* kb     = (const float*)d_in[4];
    const float* gamma  = (const float*)d_in[5];
    const float* weight = (const float*)d_in[6];
    const float* bias   = (const float*)d_in[7];
    float* out = (float*)d_out;

    cudaFuncSetAttribute(k_topk2, cudaFuncAttributeMaxDynamicSharedMemorySize, 49408);
    cudaFuncSetAttribute(k_conv,  cudaFuncAttributeMaxDynamicSharedMemorySize, 186880);

    k_prep_w<<<144, 256>>>(weight);
    k_proj<<<128, 128>>>(x, qw, qb, kw, kb);
    k_topk2<<<1024, 512, 49408>>>();
    k_conv<<<128, 512, 186880>>>(bias, gamma, out);
}

// round 10
// speedup vs baseline: 1.5879x; 1.5879x over previous
#include <cuda_runtime.h>
#include <float.h>

#define HW 4096
#define NB 4
#define FULLW 0xffffffffu

// ---------------- scratch (device globals: no allocations allowed) ----------
__device__ float g_qT[NB * HW * 8];        // [b][s][d]  512 KB
__device__ float g_kT[NB * HW * 8];        // [b][t][d]  512 KB
__device__ float g_xT[NB * HW * 64];       // [b][s][c]  4 MB
__device__ int   g_idx[NB * HW * 9];       // [b][t][9]  576 KB
__device__ float g_Wt[576 * 64];           // [kk*64+c][o] 147 KB

// ---------------- prep: weight transpose (OC,C,9) -> Wt[kk*64+c][o] ---------
__global__ void k_prep_w(const float* __restrict__ W) {
    int j = blockIdx.x * 256 + threadIdx.x;
    if (j >= 576 * 64) return;
    int r = j >> 6, o = j & 63;
    int kk = r >> 6, c = r & 63;
    g_Wt[j] = W[o * 576 + c * 9 + kk];
}

// ---------------- k1: 1x1 convs (q,k) + x transpose -------------------------
__global__ void k_proj(const float* __restrict__ x, const float* __restrict__ qw,
                       const float* __restrict__ qb, const float* __restrict__ kw,
                       const float* __restrict__ kb) {
    __shared__ float tile[64][129];
    __shared__ float wq[512], wk[512];
    int tid = threadIdx.x;
    int b  = blockIdx.x >> 5;
    int s0 = (blockIdx.x & 31) << 7;

    for (int u = tid; u < 512; u += 128) { wq[u] = qw[u]; wk[u] = kw[u]; }
    for (int u = tid; u < 64 * 128; u += 128) {
        int c = u >> 7, sl = u & 127;
        tile[c][sl] = x[(b * 64 + c) * HW + s0 + sl];
    }
    __syncthreads();

    for (int u = tid; u < 128 * 64; u += 128) {
        int sl = u >> 6, c = u & 63;
        g_xT[((size_t)b * HW + s0 + sl) * 64 + c] = tile[c][sl];
    }

    float qa[8], ka[8];
    #pragma unroll
    for (int d = 0; d < 8; ++d) { qa[d] = __ldg(qb + d); ka[d] = __ldg(kb + d); }
    int sl = tid;
    #pragma unroll 4
    for (int c = 0; c < 64; ++c) {
        float xv = tile[c][sl];
        #pragma unroll
        for (int d = 0; d < 8; ++d) {
            qa[d] = fmaf(wq[d * 64 + c], xv, qa[d]);
            ka[d] = fmaf(wk[d * 64 + c], xv, ka[d]);
        }
    }
    float4* qT4 = (float4*)g_qT;
    float4* kT4 = (float4*)g_kT;
    int base = (b * HW + s0 + sl) * 2;
    qT4[base]     = make_float4(qa[0], qa[1], qa[2], qa[3]);
    qT4[base + 1] = make_float4(qa[4], qa[5], qa[6], qa[7]);
    kT4[base]     = make_float4(ka[0], ka[1], ka[2], ka[3]);
    kT4[base + 1] = make_float4(ka[4], ka[5], ka[6], ka[7]);
}

// ---------------- k2: energy GEMM -> smem, lane-distributed top-9 -----------
// grid 1024 (4 b x 256 tiles of 16 t), block 512 (16 warps).
// Top-9 lives DISTRIBUTED across lanes 0..8 (lane j = slot j, sorted desc).
// Warp-collective insert: pos = popc(ballot(myv >= c)); shift via shfl_up;
// self-guarding (pos==9 -> no-op), fully predicated, no data-dependent branch.
__global__ void __launch_bounds__(512, 2) k_topk2() {
    extern __shared__ float sm2[];
    float4* qs4 = (float4*)sm2;            // 1024 float4 (16 KB)
    float*  ebuf = sm2 + 4096;             // 16 * 516 floats (33 KB)
    int tid  = threadIdx.x;
    int w    = tid >> 5, lane = tid & 31;
    int b    = blockIdx.x >> 8;
    int t0   = (blockIdx.x & 255) << 4;
    int tg   = lane & 15;                  // GEMM: lane -> t
    int sg   = lane >> 4;                  // GEMM: 2 s per step
    bool is9 = lane < 9;

    const float4* kT4 = (const float4*)g_kT;
    float4 kA = kT4[(b * HW + t0 + tg) * 2];
    float4 kB = kT4[(b * HW + t0 + tg) * 2 + 1];

    float myv = -FLT_MAX;                  // lane j<9: slot j (sorted desc)
    int   myix = -1;
    float th = -FLT_MAX;                   // = slot 8 value, warp-uniform

// warp-collective sorted insert of candidate C with source index SC
#define WINS(C, SC) {                                                        \
    unsigned geq = __ballot_sync(FULLW, is9 && (myv >= (C)));                \
    int pos = __popc(geq);                                                   \
    float pv = __shfl_up_sync(FULLW, myv, 1);                                \
    int  piv = __shfl_up_sync(FULLW, myix, 1);                               \
    if (is9) {                                                               \
        if (lane == pos)     { myv = (C); myix = (SC); }                     \
        else if (lane > pos) { myv = pv;  myix = piv; }                      \
    } }

    const float4* qbase = ((const float4*)g_qT) + (size_t)b * HW * 2;
    for (int chunk = 0; chunk < 8; ++chunk) {
        int s0 = chunk << 9;
        qs4[tid]       = qbase[s0 * 2 + tid];
        qs4[tid + 512] = qbase[s0 * 2 + tid + 512];
        __syncthreads();                   // q ready AND prev-chunk scans done

        #pragma unroll 4
        for (int j = 0; j < 16; ++j) {
            int sl = (w << 5) + (j << 1) + sg;
            float4 A  = qs4[sl * 2];
            float4 Bq = qs4[sl * 2 + 1];
            float e  = kA.x * A.x;
            e  = fmaf(kA.y, A.y, e);
            e  = fmaf(kA.z, A.z, e);
            e  = fmaf(kA.w, A.w, e);
            float e2 = kB.x * Bq.x;
            e2 = fmaf(kB.y, Bq.y, e2);
            e2 = fmaf(kB.z, Bq.z, e2);
            e2 = fmaf(kB.w, Bq.w, e2);
            ebuf[tg * 516 + sl] = e + e2;
        }
        __syncthreads();                   // ebuf ready

        // scan: warp w owns row w (one t)
        const float* row = ebuf + w * 516;
        #pragma unroll
        for (int g = 0; g < 4; ++g) {
            float4 ev = *(const float4*)(row + (g << 7) + (lane << 2));
            float m = fmaxf(fmaxf(ev.x, ev.y), fmaxf(ev.z, ev.w));
            unsigned bal = __ballot_sync(FULLW, m > th);
            int sb0 = s0 + (g << 7);
            while (bal) {                  // warp-uniform loop over rare hits
                int src = __ffs(bal) - 1; bal &= bal - 1;
                float c0 = __shfl_sync(FULLW, ev.x, src);
                float c1 = __shfl_sync(FULLW, ev.y, src);
                float c2 = __shfl_sync(FULLW, ev.z, src);
                float c3 = __shfl_sync(FULLW, ev.w, src);
                int sb = sb0 + (src << 2);
                WINS(c0, sb)
                WINS(c1, sb + 1)
                WINS(c2, sb + 2)
                WINS(c3, sb + 3)
            }
            th = __shfl_sync(FULLW, myv, 8);
        }
    }
#undef WINS

    // rank by index ascending; lanes 0..8 scatter-write (indices distinct)
    int r = 0;
    #pragma unroll
    for (int j = 0; j < 9; ++j) {
        int oix = __shfl_sync(FULLW, myix, j);
        if (is9 && oix < myix) r++;
    }
    if (is9)
        g_idx[((size_t)b * HW + t0 + w) * 9 + r] = myix;
}

// ---------------- k3: gather + 9-tap conv + relu + residual -----------------
// o-split: block = 128 t x 32 o (thread = 2t x 4o), W half = 73.7 KB,
// total smem 113 KB -> 2 blocks/SM (occ 50%). Register-prefetched gather.
__global__ void __launch_bounds__(512, 2) k_conv(const float* __restrict__ bias,
                                                 const float* __restrict__ gamma,
                                                 float* __restrict__ out) {
    extern __shared__ float sm[];
    float* Wsm  = sm;                          // 18432 floats (576 x 32)
    float* gbuf = sm + 18432;                  // 128 rows x 68 floats
    int*   idxs = (int*)(sm + 18432 + 128 * 68);   // 1152 ints
    int tid = threadIdx.x;
    int b   = blockIdx.x >> 6;
    int tt  = (blockIdx.x >> 1) & 31;
    int osp = blockIdx.x & 1;                  // o half
    int t0  = tt << 7;

    const float4* Wg4 = (const float4*)g_Wt;   // 576 rows x 16 f4
    float4* Ws4 = (float4*)Wsm;                // 576 rows x 8 f4
    for (int u = tid; u < 4608; u += 512)
        Ws4[u] = Wg4[((u >> 3) << 4) + (osp << 3) + (u & 7)];
    for (int u = tid; u < 1152; u += 512)
        idxs[u] = g_idx[((size_t)b * HW + t0) * 9 + u];

    int og = tid & 7;                          // 4 o each (within half)
    int tg = tid >> 3;                         // 0..63 -> 2 t each
    float4 acc0 = make_float4(0.f,0.f,0.f,0.f);
    float4 acc1 = make_float4(0.f,0.f,0.f,0.f);

    const float4* xT4 = ((const float4*)g_xT) + (size_t)b * HW * 16;
    float4* g4 = (float4*)gbuf;                // row stride 17 float4
    const float* gp0 = gbuf + (tg * 2    ) * 68;
    const float* gp1 = gbuf + (tg * 2 + 1) * 68;
    int c4  = tid & 15;                        // gather coords (indep. of compute map)
    int tl0 = tid >> 4;                        // rows tl0, +32, +64, +96
    __syncthreads();                           // idxs ready

    float4 r0 = __ldcg(&xT4[idxs[(tl0     ) * 9] * 16 + c4]);
    float4 r1 = __ldcg(&xT4[idxs[(tl0 + 32) * 9] * 16 + c4]);
    float4 r2 = __ldcg(&xT4[idxs[(tl0 + 64) * 9] * 16 + c4]);
    float4 r3 = __ldcg(&xT4[idxs[(tl0 + 96) * 9] * 16 + c4]);

#define FMA8(GA, GB, WV)                                                      \
    acc0.x = fmaf((WV).x, (GA), acc0.x); acc0.y = fmaf((WV).y, (GA), acc0.y); \
    acc0.z = fmaf((WV).z, (GA), acc0.z); acc0.w = fmaf((WV).w, (GA), acc0.w); \
    acc1.x = fmaf((WV).x, (GB), acc1.x); acc1.y = fmaf((WV).y, (GB), acc1.y); \
    acc1.z = fmaf((WV).z, (GB), acc1.z); acc1.w = fmaf((WV).w, (GB), acc1.w);

    for (int kk = 0; kk < 9; ++kk) {
        g4[(tl0     ) * 17 + c4] = r0;
        g4[(tl0 + 32) * 17 + c4] = r1;
        g4[(tl0 + 64) * 17 + c4] = r2;
        g4[(tl0 + 96) * 17 + c4] = r3;
        __syncthreads();                       // gbuf ready
        if (kk < 8) {                          // prefetch next, hidden by compute
            r0 = __ldcg(&xT4[idxs[(tl0     ) * 9 + kk + 1] * 16 + c4]);
            r1 = __ldcg(&xT4[idxs[(tl0 + 32) * 9 + kk + 1] * 16 + c4]);
            r2 = __ldcg(&xT4[idxs[(tl0 + 64) * 9 + kk + 1] * 16 + c4]);
            r3 = __ldcg(&xT4[idxs[(tl0 + 96) * 9 + kk + 1] * 16 + c4]);
        }
        int rg0 = kk << 6;
        #pragma unroll 2
        for (int rl = 0; rl < 64; rl += 4) {
            float4 ga = *(const float4*)(gp0 + rl);
            float4 gb = *(const float4*)(gp1 + rl);
            float4 w0 = Ws4[((rg0 + rl    ) << 3) + og];
            float4 w1 = Ws4[((rg0 + rl + 1) << 3) + og];
            float4 w2 = Ws4[((rg0 + rl + 2) << 3) + og];
            float4 w3 = Ws4[((rg0 + rl + 3) << 3) + og];
            FMA8(ga.x, gb.x, w0)
            FMA8(ga.y, gb.y, w1)
            FMA8(ga.z, gb.z, w2)
            FMA8(ga.w, gb.w, w3)
        }
        __syncthreads();                       // compute done before next store
    }
#undef FMA8

    float gamma0 = __ldg(gamma);
    int o0 = (osp << 5) + (og << 2);
    float4 bv = __ldg(((const float4*)bias) + (o0 >> 2));
    float4 accs[2] = {acc0, acc1};
    #pragma unroll
    for (int j = 0; j < 2; ++j) {
        int t = t0 + tg * 2 + j;
        float4 res = __ldcg(&((const float4*)g_xT)[((size_t)b * HW + t) * 16 + (o0 >> 2)]);
        float* outp = out + ((size_t)b * 64 + o0) * HW + t;
        outp[0]      = fmaf(gamma0, fmaxf(accs[j].x + bv.x, 0.f), res.x);
        outp[HW]     = fmaf(gamma0, fmaxf(accs[j].y + bv.y, 0.f), res.y);
        outp[2 * HW] = fmaf(gamma0, fmaxf(accs[j].z + bv.z, 0.f), res.z);
        outp[3 * HW] = fmaf(gamma0, fmaxf(accs[j].w + bv.w, 0.f), res.w);
    }
}

// ---------------- launch ----------------------------------------------------
extern "C" void kernel_launch(void* const* d_in, const int* in_sizes, int n_in,
                              void* d_out, int out_size) {
    const float* x      = (const float*)d_in[0];
    const float* qw     = (const float*)d_in[1];
    const float* qb     = (const float*)d_in[2];
    const float* kw     = (const float*)d_in[3];
    const float* kb     = (const float*)d_in[4];
    const float* gamma  = (const float*)d_in[5];
    const float* weight = (const float*)d_in[6];
    const float* bias   = (const float*)d_in[7];
    float* out = (float*)d_out;

    // k_topk2: 49408 B ; k_conv: (18432 + 8704)*4 + 4608 = 113152 B
    cudaFuncSetAttribute(k_topk2, cudaFuncAttributeMaxDynamicSharedMemorySize, 49408);
    cudaFuncSetAttribute(k_conv,  cudaFuncAttributeMaxDynamicSharedMemorySize, 113152);

    k_prep_w<<<144, 256>>>(weight);
    k_proj<<<128, 128>>>(x, qw, qb, kw, kb);
    k_topk2<<<1024, 512, 49408>>>();
    k_conv<<<256, 512, 113152>>>(bias, gamma, out);
}

// round 14
// speedup vs baseline: 2.0356x; 1.2820x over previous
#include <cuda_runtime.h>
#include <float.h>

#define HW 4096
#define NB 4
#define FULLW 0xffffffffu

// ---------------- scratch (device globals: no allocations allowed) ----------
__device__ float g_qT[NB * HW * 8];        // [b][s][d]  512 KB
__device__ float g_kT[NB * HW * 8];        // [b][t][d]  512 KB
__device__ float g_xT[NB * HW * 64];       // [b][s][c]  4 MB
__device__ int   g_idx[NB * HW * 9];       // [b][t][9]  576 KB
__device__ float g_Wt[576 * 64];           // [kk*64+c][o] 147 KB

// ---------------- prep: weight transpose (OC,C,9) -> Wt[kk*64+c][o] ---------
__global__ void k_prep_w(const float* __restrict__ W) {
    int j = blockIdx.x * 256 + threadIdx.x;
    if (j >= 576 * 64) return;
    int r = j >> 6, o = j & 63;
    int kk = r >> 6, c = r & 63;
    g_Wt[j] = W[o * 576 + c * 9 + kk];
}

// ---------------- k1: 1x1 convs (q,k) + x transpose -------------------------
__global__ void k_proj(const float* __restrict__ x, const float* __restrict__ qw,
                       const float* __restrict__ qb, const float* __restrict__ kw,
                       const float* __restrict__ kb) {
    __shared__ float tile[64][129];
    __shared__ float wq[512], wk[512];
    int tid = threadIdx.x;
    int b  = blockIdx.x >> 5;
    int s0 = (blockIdx.x & 31) << 7;

    for (int u = tid; u < 512; u += 128) { wq[u] = qw[u]; wk[u] = kw[u]; }
    for (int u = tid; u < 64 * 128; u += 128) {
        int c = u >> 7, sl = u & 127;
        tile[c][sl] = x[(b * 64 + c) * HW + s0 + sl];
    }
    __syncthreads();

    for (int u = tid; u < 128 * 64; u += 128) {
        int sl = u >> 6, c = u & 63;
        g_xT[((size_t)b * HW + s0 + sl) * 64 + c] = tile[c][sl];
    }

    float qa[8], ka[8];
    #pragma unroll
    for (int d = 0; d < 8; ++d) { qa[d] = __ldg(qb + d); ka[d] = __ldg(kb + d); }
    int sl = tid;
    #pragma unroll 4
    for (int c = 0; c < 64; ++c) {
        float xv = tile[c][sl];
        #pragma unroll
        for (int d = 0; d < 8; ++d) {
            qa[d] = fmaf(wq[d * 64 + c], xv, qa[d]);
            ka[d] = fmaf(wk[d * 64 + c], xv, ka[d]);
        }
    }
    float4* qT4 = (float4*)g_qT;
    float4* kT4 = (float4*)g_kT;
    int base = (b * HW + s0 + sl) * 2;
    qT4[base]     = make_float4(qa[0], qa[1], qa[2], qa[3]);
    qT4[base + 1] = make_float4(qa[4], qa[5], qa[6], qa[7]);
    kT4[base]     = make_float4(ka[0], ka[1], ka[2], ka[3]);
    kT4[base + 1] = make_float4(ka[4], ka[5], ka[6], ka[7]);
}

// ---------------- k2: energy GEMM -> smem, lane-distributed top-9 -----------
// Top-9 distributed across lanes 0..8 (lane j = slot j, sorted desc).
// Scan uses PER-COMPONENT ballots with th refreshed after each round: the
// chunk-0 storm collapses (round x primes th, rounds y/z/w see few hits).
__global__ void __launch_bounds__(512, 2) k_topk2() {
    extern __shared__ float sm2[];
    float4* qs4 = (float4*)sm2;            // 1024 float4 (16 KB)
    float*  ebuf = sm2 + 4096;             // 16 * 516 floats (33 KB)
    int tid  = threadIdx.x;
    int w    = tid >> 5, lane = tid & 31;
    int b    = blockIdx.x >> 8;
    int t0   = (blockIdx.x & 255) << 4;
    int tg   = lane & 15;                  // GEMM: lane -> t
    int sg   = lane >> 4;                  // GEMM: 2 s per step
    bool is9 = lane < 9;

    const float4* kT4 = (const float4*)g_kT;
    float4 kA = kT4[(b * HW + t0 + tg) * 2];
    float4 kB = kT4[(b * HW + t0 + tg) * 2 + 1];

    float myv = -FLT_MAX;                  // lane j<9: slot j (sorted desc)
    int   myix = -1;
    float th = -FLT_MAX;                   // = slot 8 value, warp-uniform

// warp-collective sorted insert (self-guarding: pos==9 -> no-op)
#define WINS(C, SC) {                                                        \
    unsigned geq = __ballot_sync(FULLW, is9 && (myv >= (C)));                \
    int pos = __popc(geq);                                                   \
    float pv = __shfl_up_sync(FULLW, myv, 1);                                \
    int  piv = __shfl_up_sync(FULLW, myix, 1);                               \
    if (is9) {                                                               \
        if (lane == pos)     { myv = (C); myix = (SC); }                     \
        else if (lane > pos) { myv = pv;  myix = piv; }                      \
    } }

// one component round: scalar ballot, pop hits, refresh threshold
#define PROC(C, SGB) {                                                       \
    unsigned bal = __ballot_sync(FULLW, (C) > th);                           \
    while (bal) {                                                            \
        int src = __ffs(bal) - 1; bal &= bal - 1;                            \
        float cv = __shfl_sync(FULLW, (C), src);                             \
        WINS(cv, (SGB) + (src << 2))                                         \
    }                                                                        \
    th = __shfl_sync(FULLW, myv, 8);                                         \
}

    const float4* qbase = ((const float4*)g_qT) + (size_t)b * HW * 2;
    for (int chunk = 0; chunk < 8; ++chunk) {
        int s0 = chunk << 9;
        qs4[tid]       = qbase[s0 * 2 + tid];
        qs4[tid + 512] = qbase[s0 * 2 + tid + 512];
        __syncthreads();                   // q ready AND prev-chunk scans done

        #pragma unroll 4
        for (int j = 0; j < 16; ++j) {
            int sl = (w << 5) + (j << 1) + sg;
            float4 A  = qs4[sl * 2];
            float4 Bq = qs4[sl * 2 + 1];
            float e  = kA.x * A.x;
            e  = fmaf(kA.y, A.y, e);
            e  = fmaf(kA.z, A.z, e);
            e  = fmaf(kA.w, A.w, e);
            float e2 = kB.x * Bq.x;
            e2 = fmaf(kB.y, Bq.y, e2);
            e2 = fmaf(kB.z, Bq.z, e2);
            e2 = fmaf(kB.w, Bq.w, e2);
            ebuf[tg * 516 + sl] = e + e2;
        }
        __syncthreads();                   // ebuf ready

        // scan: warp w owns row w (one t)
        const float* row = ebuf + w * 516;
        #pragma unroll
        for (int g = 0; g < 4; ++g) {
            float4 ev = *(const float4*)(row + (g << 7) + (lane << 2));
            int sgb = s0 + (g << 7);
            PROC(ev.x, sgb)
            PROC(ev.y, sgb + 1)
            PROC(ev.z, sgb + 2)
            PROC(ev.w, sgb + 3)
        }
    }
#undef PROC
#undef WINS

    // rank by index ascending; lanes 0..8 scatter-write (indices distinct)
    int r = 0;
    #pragma unroll
    for (int j = 0; j < 9; ++j) {
        int oix = __shfl_sync(FULLW, myix, j);
        if (is9 && oix < myix) r++;
    }
    if (is9)
        g_idx[((size_t)b * HW + t0 + w) * 9 + r] = myix;
}

// ---------------- k3: gather + 9-tap conv + relu + residual -----------------
// 128 t x 64 o per block (thread = 4t x 4o), double-buffered gather buffer:
// one __syncthreads per kk; STS of kk+1 overlaps compute of kk; LDG prefetch
// a full compute phase ahead. (GLOAD/GSTORE are braced blocks — R11's crash
// was an unbraced GLOAD under `if`, guarding only its first statement.)
__global__ void __launch_bounds__(512, 1) k_conv(const float* __restrict__ bias,
                                                 const float* __restrict__ gamma,
                                                 float* __restrict__ out) {
    extern __shared__ float sm[];
    float* Wsm   = sm;                         // 36864 floats
    float* gbufA = sm + 36864;                 // 128 x 68
    float* gbufB = gbufA + 8704;               // 128 x 68
    int*   idxs  = (int*)(gbufB + 8704);       // 1152 ints
    int tid = threadIdx.x;
    int b  = blockIdx.x >> 5;
    int t0 = (blockIdx.x & 31) << 7;

    for (int u = tid; u < 36864; u += 512) Wsm[u] = g_Wt[u];
    for (int u = tid; u < 1152; u += 512)
        idxs[u] = g_idx[((size_t)b * HW + t0) * 9 + u];

    int og = tid & 15;
    int tg = tid >> 4;
    float4 acc0 = make_float4(0.f,0.f,0.f,0.f);
    float4 acc1 = make_float4(0.f,0.f,0.f,0.f);
    float4 acc2 = make_float4(0.f,0.f,0.f,0.f);
    float4 acc3 = make_float4(0.f,0.f,0.f,0.f);

    const float4* xT4 = ((const float4*)g_xT) + (size_t)b * HW * 16;
    const float4* W4  = (const float4*)Wsm;
    int c4  = tid & 15;
    int tl0 = tid >> 4;
    __syncthreads();                           // idxs ready

#define GLOAD(KK) {                                                          \
    r0 = __ldcg(&xT4[idxs[(tl0     ) * 9 + (KK)] * 16 + c4]);                \
    r1 = __ldcg(&xT4[idxs[(tl0 + 32) * 9 + (KK)] * 16 + c4]);                \
    r2 = __ldcg(&xT4[idxs[(tl0 + 64) * 9 + (KK)] * 16 + c4]);                \
    r3 = __ldcg(&xT4[idxs[(tl0 + 96) * 9 + (KK)] * 16 + c4]); }

#define GSTORE(BUF) {                                                        \
    float4* n4 = (float4*)(BUF);                                             \
    n4[(tl0     ) * 17 + c4] = r0;                                           \
    n4[(tl0 + 32) * 17 + c4] = r1;                                           \
    n4[(tl0 + 64) * 17 + c4] = r2;                                           \
    n4[(tl0 + 96) * 17 + c4] = r3; }

    float4 r0, r1, r2, r3;
    GLOAD(0)
    GSTORE(gbufA)
    GLOAD(1)
    __syncthreads();                           // gbufA visible; r holds kk=1

    for (int kk = 0; kk < 9; ++kk) {
        float* cur = (kk & 1) ? gbufB : gbufA;
        float* nxt = (kk & 1) ? gbufA : gbufB;
        if (kk < 8) GSTORE(nxt)                // r = kk+1 data
        if (kk < 7) GLOAD(kk + 2)              // prefetch a full phase ahead
        const float* gp0 = cur + (tg * 4 + 0) * 68;
        const float* gp1 = cur + (tg * 4 + 1) * 68;
        const float* gp2 = cur + (tg * 4 + 2) * 68;
        const float* gp3 = cur + (tg * 4 + 3) * 68;
        int rg0 = kk << 6;
        #pragma unroll 4
        for (int rl = 0; rl < 64; ++rl) {
            float4 wv = W4[((rg0 + rl) << 4) + og];
            float gA = gp0[rl];
            float gB = gp1[rl];
            float gC = gp2[rl];
            float gD = gp3[rl];
            acc0.x = fmaf(wv.x, gA, acc0.x); acc0.y = fmaf(wv.y, gA, acc0.y);
            acc0.z = fmaf(wv.z, gA, acc0.z); acc0.w = fmaf(wv.w, gA, acc0.w);
            acc1.x = fmaf(wv.x, gB, acc1.x); acc1.y = fmaf(wv.y, gB, acc1.y);
            acc1.z = fmaf(wv.z, gB, acc1.z); acc1.w = fmaf(wv.w, gB, acc1.w);
            acc2.x = fmaf(wv.x, gC, acc2.x); acc2.y = fmaf(wv.y, gC, acc2.y);
            acc2.z = fmaf(wv.z, gC, acc2.z); acc2.w = fmaf(wv.w, gC, acc2.w);
            acc3.x = fmaf(wv.x, gD, acc3.x); acc3.y = fmaf(wv.y, gD, acc3.y);
            acc3.z = fmaf(wv.z, gD, acc3.z); acc3.w = fmaf(wv.w, gD, acc3.w);
        }
        __syncthreads();                       // nxt stored & cur reads done
    }
#undef GLOAD
#undef GSTORE

    float gamma0 = __ldg(gamma);
    float4 bv = __ldg(((const float4*)bias) + og);
    int o0 = og << 2;
    float4 accs[4] = {acc0, acc1, acc2, acc3};
    #pragma unroll
    for (int j = 0; j < 4; ++j) {
        int t = t0 + tg * 4 + j;
        float4 res = __ldcg(&((const float4*)g_xT)[((size_t)b * HW + t) * 16 + og]);
        float* outp = out + ((size_t)b * 64 + o0) * HW + t;
        outp[0]      = fmaf(gamma0, fmaxf(accs[j].x + bv.x, 0.f), res.x);
        outp[HW]     = fmaf(gamma0, fmaxf(accs[j].y + bv.y, 0.f), res.y);
        outp[2 * HW] = fmaf(gamma0, fmaxf(accs[j].z + bv.z, 0.f), res.z);
        outp[3 * HW] = fmaf(gamma0, fmaxf(accs[j].w + bv.w, 0.f), res.w);
    }
}

// ---------------- launch ----------------------------------------------------
extern "C" void kernel_launch(void* const* d_in, const int* in_sizes, int n_in,
                              void* d_out, int out_size) {
    const float* x      = (const float*)d_in[0];
    const float* qw     = (const float*)d_in[1];
    const float* qb     = (const float*)d_in[2];
    const float* kw     = (const float*)d_in[3];
    const float* kb     = (const float*)d_in[4];
    const float* gamma  = (const float*)d_in[5];
    const float* weight = (const float*)d_in[6];
    const float* bias   = (const float*)d_in[7];
    float* out = (float*)d_out;

    // k_topk2: 49408 B ; k_conv: (36864 + 2*8704)*4 + 4608 = 221696 B
    cudaFuncSetAttribute(k_topk2, cudaFuncAttributeMaxDynamicSharedMemorySize, 49408);
    cudaFuncSetAttribute(k_conv,  cudaFuncAttributeMaxDynamicSharedMemorySize, 221696);

    k_prep_w<<<144, 256>>>(weight);
    k_proj<<<128, 128>>>(x, qw, qb, kw, kb);
    k_topk2<<<1024, 512, 49408>>>();
    k_conv<<<128, 512, 221696>>>(bias, gamma, out);
}